// round 15
// baseline (speedup 1.0000x reference)
#include <cuda_runtime.h>
#include <cuda_bf16.h>
#include <math.h>

#define NNODES 100000
#define NEDGES 1000000
#define F0 256
#define F1 64
#define F2 40
#define SCAN_B 512
#define NB ((NNODES + SCAN_B - 1) / SCAN_B)   // 196
#define AGG_TILE 2048

// ---------------- scratch (static device globals; no allocation) ----------------
__device__ uint2 d_g1[NNODES * 16];    // u1 = x @ W1, bf16x4 per uint2 (64 vals/row)
__device__ float d_h1[NNODES * F1];    // relu layer-1 output (fp32, GEMM2 input)
__device__ uint2 d_g2[NNODES * 10];    // u2 = h1 @ W2, bf16 (40 vals/row)
__device__ float d_h2[NNODES * F2];
__device__ float d_colsum[64];
__device__ float d_dinv[NNODES];
__device__ int   d_csrc[NEDGES];
__device__ int   d_cnt[NNODES];        // zero at t=0; re-zeroed by k_scan2b each run
__device__ int   d_rowptr[NNODES + 1];
__device__ int   d_cursor[NNODES];
__device__ int   d_blocksum[NB];

// ---------------- per-block int64/int32 detection helper ----------------
__device__ __forceinline__ int detect_is64(const void* e, int t) {
    __shared__ int s_is64;
    if (t < 32) {
        const long long* e64 = (const long long*)e;
        long long v0 = e64[t];
        long long v1 = e64[t + 32];
        bool ok = (v0 >= 0 && v0 < NNODES) && (v1 >= 0 && v1 < NNODES);
        unsigned m = __ballot_sync(0xffffffffu, ok);
        if (t == 0) s_is64 = (m == 0xffffffffu) ? 1 : 0;
    }
    __syncthreads();
    return s_is64;
}

// ---------------- per-dst histogram (reads raw edge list) ----------------
__global__ void k_count(const void* __restrict__ e) {
    int t = threadIdx.x;
    int is64 = detect_is64(e, t);
    int idx = blockIdx.x * blockDim.x + t;
    if (idx >= NEDGES) return;
    int d = is64 ? (int)((const long long*)e)[NEDGES + idx]
                 : ((const int*)e)[NEDGES + idx];
    atomicAdd(&d_cnt[d], 1);
}

// ---------------- scan stage 1: per-block exclusive scan + block sums ----------------
__global__ void k_scan1() {
    __shared__ int sm[SCAN_B];
    int base = blockIdx.x * SCAN_B;
    int t = threadIdx.x;
    int v = (base + t < NNODES) ? d_cnt[base + t] : 0;
    sm[t] = v;
    __syncthreads();
    for (int o = 1; o < SCAN_B; o <<= 1) {
        int a = (t >= o) ? sm[t - o] : 0;
        __syncthreads();
        sm[t] += a;
        __syncthreads();
    }
    if (base + t < NNODES) d_rowptr[base + t] = sm[t] - v;
    if (t == SCAN_B - 1) d_blocksum[blockIdx.x] = sm[t];
}

// ---------------- scan stage 2 (fused fixup) ----------------
__global__ void k_scan2b() {
    __shared__ int sm[256];
    __shared__ int soff[NB];
    int t = threadIdx.x;
    int v = (t < NB) ? d_blocksum[t] : 0;
    sm[t] = v;
    __syncthreads();
    for (int o = 1; o < 256; o <<= 1) {
        int a = (t >= o) ? sm[t - o] : 0;
        __syncthreads();
        sm[t] += a;
        __syncthreads();
    }
    if (t < NB) soff[t] = sm[t] - v;
    if (blockIdx.x == 0 && t < 64) d_colsum[t] = 0.f;
    __syncthreads();
    int i = blockIdx.x * blockDim.x + t;
    if (i >= NNODES) return;
    int rp = d_rowptr[i] + soff[i / SCAN_B];
    d_rowptr[i] = rp;
    d_cursor[i] = rp;
    d_dinv[i] = rsqrtf(1.0f + (float)d_cnt[i]);
    d_cnt[i] = 0;                           // reset for next graph replay
    if (i == 0) d_rowptr[NNODES] = NEDGES;
}

// ---------------- fill CSR (reads raw edge list) ----------------
__global__ void k_fill(const void* __restrict__ e) {
    int t = threadIdx.x;
    int is64 = detect_is64(e, t);
    int idx = blockIdx.x * blockDim.x + t;
    if (idx >= NEDGES) return;
    int s, d;
    if (is64) {
        s = (int)((const long long*)e)[idx];
        d = (int)((const long long*)e)[NEDGES + idx];
    } else {
        s = ((const int*)e)[idx];
        d = ((const int*)e)[NEDGES + idx];
    }
    int pos = atomicAdd(&d_cursor[d], 1);
    d_csrc[pos] = s;
}

// ---------------- TF32 GEMM with cp.async double buffering: C = A@B ----------------
#define CP_A16(dst, src, sz) \
    asm volatile("cp.async.ca.shared.global [%0], [%1], 16, %2;" \
                 :: "r"(dst), "l"(src), "r"(sz))

template <bool BF16OUT>
__global__ __launch_bounds__(256) void k_gemm_tf32(
    const float* __restrict__ A, const float* __restrict__ B,
    void* __restrict__ C, int M, int N, int K) {
    const int BM = 128, BK = 16, PA = 4, PB = 8;
    __shared__ float As[2][BM][BK + PA];
    __shared__ float Bs[2][BK][64 + PB];
    int tid = threadIdx.x;
    int rowBase = blockIdx.x * BM;
    int warpId = tid >> 5, lane = tid & 31;
    int g = lane >> 2, t4 = lane & 3;
    int m0 = (warpId & 3) * 32, n0 = (warpId >> 2) * 32;

    int ar0 = tid >> 2;
    int ac  = (tid & 3) * 4;
    int br  = tid >> 4;
    int bc  = (tid & 15) * 4;

    float acc[2][4][4];
#pragma unroll
    for (int mt = 0; mt < 2; mt++)
#pragma unroll
        for (int nt = 0; nt < 4; nt++)
#pragma unroll
            for (int i = 0; i < 4; i++) acc[mt][nt][i] = 0.f;

    int nIter = K / BK;

    auto prefetch = [&](int it, int st) {
#pragma unroll
        for (int v = 0; v < 2; v++) {
            int row = ar0 + v * 64;
            int gr = rowBase + row;
            unsigned dst = (unsigned)__cvta_generic_to_shared(&As[st][row][ac]);
            const float* src = A + (size_t)(gr < M ? gr : 0) * K + it * BK + ac;
            CP_A16(dst, src, (gr < M) ? 16 : 0);
        }
        {
            unsigned dst = (unsigned)__cvta_generic_to_shared(&Bs[st][br][bc]);
            int ok = (bc + 3 < N);
            const float* src = B + (size_t)(it * BK + br) * N + (ok ? bc : 0);
            CP_A16(dst, src, ok ? 16 : 0);
        }
    };

    prefetch(0, 0);
    asm volatile("cp.async.commit_group;" ::: "memory");

    for (int it = 0; it < nIter; it++) {
        int st = it & 1;
        if (it + 1 < nIter) {
            prefetch(it + 1, st ^ 1);
            asm volatile("cp.async.commit_group;" ::: "memory");
            asm volatile("cp.async.wait_group 1;" ::: "memory");
        } else {
            asm volatile("cp.async.wait_group 0;" ::: "memory");
        }
        __syncthreads();
#pragma unroll
        for (int ks = 0; ks < 2; ks++) {
            int kb = ks * 8;
            unsigned af[2][4], bf[4][2];
#pragma unroll
            for (int mt = 0; mt < 2; mt++) {
                int m = m0 + mt * 16 + g;
                af[mt][0] = __float_as_uint(As[st][m][kb + t4]);
                af[mt][1] = __float_as_uint(As[st][m + 8][kb + t4]);
                af[mt][2] = __float_as_uint(As[st][m][kb + t4 + 4]);
                af[mt][3] = __float_as_uint(As[st][m + 8][kb + t4 + 4]);
            }
#pragma unroll
            for (int nt = 0; nt < 4; nt++) {
                int n = n0 + nt * 8 + g;
                bf[nt][0] = __float_as_uint(Bs[st][kb + t4][n]);
                bf[nt][1] = __float_as_uint(Bs[st][kb + t4 + 4][n]);
            }
#pragma unroll
            for (int mt = 0; mt < 2; mt++)
#pragma unroll
                for (int nt = 0; nt < 4; nt++) {
                    asm volatile(
                        "mma.sync.aligned.m16n8k8.row.col.f32.tf32.tf32.f32 "
                        "{%0,%1,%2,%3}, {%4,%5,%6,%7}, {%8,%9}, {%0,%1,%2,%3};"
                        : "+f"(acc[mt][nt][0]), "+f"(acc[mt][nt][1]),
                          "+f"(acc[mt][nt][2]), "+f"(acc[mt][nt][3])
                        : "r"(af[mt][0]), "r"(af[mt][1]), "r"(af[mt][2]), "r"(af[mt][3]),
                          "r"(bf[nt][0]), "r"(bf[nt][1]));
                }
        }
        __syncthreads();
    }

#pragma unroll
    for (int mt = 0; mt < 2; mt++) {
#pragma unroll
        for (int half = 0; half < 2; half++) {
            int r = rowBase + m0 + mt * 16 + half * 8 + g;
            if (r >= M) continue;
#pragma unroll
            for (int nt = 0; nt < 4; nt++) {
                int c = n0 + nt * 8 + 2 * t4;
                if (c < N) {
                    float ox = acc[mt][nt][half * 2 + 0];
                    float oy = acc[mt][nt][half * 2 + 1];
                    if (BF16OUT) {
                        __nv_bfloat162 p = __float22bfloat162_rn(make_float2(ox, oy));
                        ((unsigned*)C)[(size_t)r * (N / 2) + (c >> 1)] = *(unsigned*)&p;
                    } else {
                        *(float2*)((float*)C + (size_t)r * N + c) = make_float2(ox, oy);
                    }
                }
            }
        }
    }
}

// ---------------- bf16x4 -> float4 helper ----------------
__device__ __forceinline__ float4 bf16x4_to_f4(uint2 raw) {
    float2 a = __bfloat1622float2(*(__nv_bfloat162*)&raw.x);
    float2 b = __bfloat1622float2(*(__nv_bfloat162*)&raw.y);
    return make_float4(a.x, a.y, b.x, b.y);
}

// ---------------- layer-1 aggregation with smem index/weight staging ----------------
// Block = 16 nodes x 16 lanes. Stage (csrc, dinv[csrc]) for the block's contiguous
// CSR range in smem; inner loop reads idx+w from smem, only g1 rows from L2.
__global__ __launch_bounds__(256) void k_agg1(const float* __restrict__ b1) {
    __shared__ int   s_idx[AGG_TILE];
    __shared__ float s_w[AGG_TILE];
    int t = threadIdx.x;
    int gBase = blockIdx.x * 16;
    int g = gBase + (t >> 4);
    int lane = t & 15;
    bool valid = g < NNODES;

    int blockStart = d_rowptr[gBase];
    int gTop = gBase + 16;
    int blockEnd = d_rowptr[gTop > NNODES ? NNODES : gTop];

    int start = 0, end = 0;
    float sd = 0.f;
    float4 acc = make_float4(0.f, 0.f, 0.f, 0.f);
    if (valid) {
        start = d_rowptr[g];
        end = d_rowptr[g + 1];
        sd = d_dinv[g];
        float4 u = bf16x4_to_f4(__ldg(&d_g1[(size_t)g * 16 + lane]));
        acc = make_float4(sd * u.x, sd * u.y, sd * u.z, sd * u.w);   // self loop
    }

    for (int tb = blockStart; tb < blockEnd; tb += AGG_TILE) {
        int tileN = blockEnd - tb;
        if (tileN > AGG_TILE) tileN = AGG_TILE;
        __syncthreads();
        for (int i = t; i < tileN; i += 256) {
            int s = __ldg(&d_csrc[tb + i]);
            s_idx[i] = s;
            s_w[i] = __ldg(&d_dinv[s]);
        }
        __syncthreads();
        if (valid) {
            int lo = (start > tb ? start : tb) - tb;
            int hiAbs = end < tb + tileN ? end : tb + tileN;
            int hi = hiAbs - tb;
            int e = lo;
            for (; e + 3 < hi; e += 4) {
                int s0 = s_idx[e],     s1 = s_idx[e + 1];
                int s2 = s_idx[e + 2], s3 = s_idx[e + 3];
                float w0 = s_w[e],     w1 = s_w[e + 1];
                float w2 = s_w[e + 2], w3 = s_w[e + 3];
                float4 v0 = bf16x4_to_f4(__ldg(&d_g1[(size_t)s0 * 16 + lane]));
                float4 v1 = bf16x4_to_f4(__ldg(&d_g1[(size_t)s1 * 16 + lane]));
                float4 v2 = bf16x4_to_f4(__ldg(&d_g1[(size_t)s2 * 16 + lane]));
                float4 v3 = bf16x4_to_f4(__ldg(&d_g1[(size_t)s3 * 16 + lane]));
                acc.x += w0 * v0.x + w1 * v1.x + w2 * v2.x + w3 * v3.x;
                acc.y += w0 * v0.y + w1 * v1.y + w2 * v2.y + w3 * v3.y;
                acc.z += w0 * v0.z + w1 * v1.z + w2 * v2.z + w3 * v3.z;
                acc.w += w0 * v0.w + w1 * v1.w + w2 * v2.w + w3 * v3.w;
            }
            for (; e < hi; e++) {
                int s0 = s_idx[e];
                float w0 = s_w[e];
                float4 v = bf16x4_to_f4(__ldg(&d_g1[(size_t)s0 * 16 + lane]));
                acc.x += w0 * v.x; acc.y += w0 * v.y;
                acc.z += w0 * v.z; acc.w += w0 * v.w;
            }
        }
    }

    if (valid) {
        int c = lane * 4;
        float4 o;
        o.x = fmaxf(sd * acc.x + __ldg(b1 + c + 0), 0.f);
        o.y = fmaxf(sd * acc.y + __ldg(b1 + c + 1), 0.f);
        o.z = fmaxf(sd * acc.z + __ldg(b1 + c + 2), 0.f);
        o.w = fmaxf(sd * acc.w + __ldg(b1 + c + 3), 0.f);
        ((float4*)d_h1)[(size_t)g * 16 + lane] = o;
    }
}

// ---------------- layer-2 aggregation with staging + bias + column sums ----------------
__global__ __launch_bounds__(256) void k_agg2(const float* __restrict__ b2) {
    __shared__ int   s_idx[AGG_TILE];
    __shared__ float s_w[AGG_TILE];
    __shared__ float scol[F2];
    int t = threadIdx.x;
    if (t < F2) scol[t] = 0.f;
    int gBase = blockIdx.x * 16;
    int g = gBase + (t >> 4);
    int lane = t & 15;
    bool valid = (g < NNODES) && (lane < 10);

    int blockStart = d_rowptr[gBase];
    int gTop = gBase + 16;
    int blockEnd = d_rowptr[gTop > NNODES ? NNODES : gTop];

    int start = 0, end = 0;
    float sd = 0.f;
    float4 acc = make_float4(0.f, 0.f, 0.f, 0.f);
    if (valid) {
        start = d_rowptr[g];
        end = d_rowptr[g + 1];
        sd = d_dinv[g];
        float4 u = bf16x4_to_f4(__ldg(&d_g2[(size_t)g * 10 + lane]));
        acc = make_float4(sd * u.x, sd * u.y, sd * u.z, sd * u.w);
    }

    for (int tb = blockStart; tb < blockEnd; tb += AGG_TILE) {
        int tileN = blockEnd - tb;
        if (tileN > AGG_TILE) tileN = AGG_TILE;
        __syncthreads();
        for (int i = t; i < tileN; i += 256) {
            int s = __ldg(&d_csrc[tb + i]);
            s_idx[i] = s;
            s_w[i] = __ldg(&d_dinv[s]);
        }
        __syncthreads();
        if (valid) {
            int lo = (start > tb ? start : tb) - tb;
            int hiAbs = end < tb + tileN ? end : tb + tileN;
            int hi = hiAbs - tb;
            int e = lo;
            for (; e + 1 < hi; e += 2) {
                int s0 = s_idx[e], s1 = s_idx[e + 1];
                float w0 = s_w[e], w1 = s_w[e + 1];
                float4 v0 = bf16x4_to_f4(__ldg(&d_g2[(size_t)s0 * 10 + lane]));
                float4 v1 = bf16x4_to_f4(__ldg(&d_g2[(size_t)s1 * 10 + lane]));
                acc.x += w0 * v0.x + w1 * v1.x;
                acc.y += w0 * v0.y + w1 * v1.y;
                acc.z += w0 * v0.z + w1 * v1.z;
                acc.w += w0 * v0.w + w1 * v1.w;
            }
            if (e < hi) {
                int s0 = s_idx[e];
                float w0 = s_w[e];
                float4 v = bf16x4_to_f4(__ldg(&d_g2[(size_t)s0 * 10 + lane]));
                acc.x += w0 * v.x; acc.y += w0 * v.y;
                acc.z += w0 * v.z; acc.w += w0 * v.w;
            }
        }
    }

    __syncthreads();
    if (valid) {
        int c = lane * 4;
        float4 o;
        o.x = sd * acc.x + __ldg(b2 + c + 0);
        o.y = sd * acc.y + __ldg(b2 + c + 1);
        o.z = sd * acc.z + __ldg(b2 + c + 2);
        o.w = sd * acc.w + __ldg(b2 + c + 3);
        ((float4*)d_h2)[(size_t)g * 10 + lane] = o;
        atomicAdd(&scol[c + 0], o.x);
        atomicAdd(&scol[c + 1], o.y);
        atomicAdd(&scol[c + 2], o.z);
        atomicAdd(&scol[c + 3], o.w);
    }
    __syncthreads();
    if (t < F2) atomicAdd(&d_colsum[t], scol[t]);
}

// ---------------- PairNorm-SI + log_softmax, one warp per row ----------------
__global__ void k_final(float* __restrict__ out) {
    int gt = blockIdx.x * blockDim.x + threadIdx.x;
    int row = gt >> 5;
    int lane = gt & 31;
    if (row >= NNODES) return;
    const float invN = 1.0f / (float)NNODES;
    bool has2 = lane < (F2 - 32);
    float y0 = d_h2[(size_t)row * F2 + lane] - d_colsum[lane] * invN;
    float y1 = 0.f;
    if (has2) y1 = d_h2[(size_t)row * F2 + 32 + lane] - d_colsum[32 + lane] * invN;
    float ss = y0 * y0 + y1 * y1;
#pragma unroll
    for (int o = 16; o; o >>= 1) ss += __shfl_xor_sync(0xffffffffu, ss, o);
    float inv = rsqrtf(1e-6f + ss);
    float z0 = y0 * inv;
    float z1 = has2 ? y1 * inv : -1e30f;
    float mx = fmaxf(z0, z1);
#pragma unroll
    for (int o = 16; o; o >>= 1) mx = fmaxf(mx, __shfl_xor_sync(0xffffffffu, mx, o));
    float se = expf(z0 - mx) + (has2 ? expf(z1 - mx) : 0.f);
#pragma unroll
    for (int o = 16; o; o >>= 1) se += __shfl_xor_sync(0xffffffffu, se, o);
    float lse = logf(se);
    out[(size_t)row * F2 + lane] = z0 - mx - lse;
    if (has2) out[(size_t)row * F2 + 32 + lane] = z1 - mx - lse;
}

// ---------------- launch ----------------
extern "C" void kernel_launch(void* const* d_in, const int* in_sizes, int n_in,
                              void* d_out, int out_size) {
    const float* x   = (const float*)d_in[0];
    const void*  eix = d_in[1];
    const float* W1  = (const float*)d_in[2];
    const float* b1  = (const float*)d_in[3];
    const float* W2  = (const float*)d_in[4];
    const float* b2  = (const float*)d_in[5];
    float* out = (float*)d_out;

    static cudaStream_t s_aux = []() {
        cudaStream_t s; cudaStreamCreateWithFlags(&s, cudaStreamNonBlocking); return s;
    }();
    static cudaEvent_t e_fork = []() {
        cudaEvent_t e; cudaEventCreateWithFlags(&e, cudaEventDisableTiming); return e;
    }();
    static cudaEvent_t e_join = []() {
        cudaEvent_t e; cudaEventCreateWithFlags(&e, cudaEventDisableTiming); return e;
    }();

    void *g1, *g2;
    float *h1;
    cudaGetSymbolAddress(&g1, d_g1);
    cudaGetSymbolAddress((void**)&h1, d_h1);
    cudaGetSymbolAddress(&g2, d_g2);

    const int T = 256;

    // Fork: GEMM1 enqueued FIRST on aux stream so it wins SMs and overlaps CSR build
    cudaEventRecord(e_fork, 0);
    cudaStreamWaitEvent(s_aux, e_fork, 0);
    k_gemm_tf32<true><<<(NNODES + 127) / 128, 256, 0, s_aux>>>(x, W1, g1, NNODES, F1, F0);
    cudaEventRecord(e_join, s_aux);

    // CSR build on the main stream
    k_count<<<(NEDGES + T - 1) / T, T>>>(eix);
    k_scan1<<<NB, SCAN_B>>>();
    k_scan2b<<<(NNODES + 255) / 256, 256>>>();
    k_fill<<<(NEDGES + T - 1) / T, T>>>(eix);

    // Join, then the dependent chain
    cudaStreamWaitEvent(0, e_join, 0);
    k_agg1<<<(NNODES + 15) / 16, 256>>>(b1);
    k_gemm_tf32<true><<<(NNODES + 127) / 128, 256>>>(h1, W2, g2, NNODES, F2, F1);
    k_agg2<<<(NNODES + 15) / 16, 256>>>(b2);
    k_final<<<((long long)NNODES * 32 + T - 1) / T, T>>>(out);
}

// round 16
// speedup vs baseline: 1.0836x; 1.0836x over previous
#include <cuda_runtime.h>
#include <cuda_bf16.h>
#include <math.h>

#define NNODES 100000
#define NEDGES 1000000
#define F0 256
#define F1 64
#define F2 40
#define LBB 1024
#define LBN ((NNODES + LBB - 1) / LBB)   // 98 partitions

// ---------------- scratch (static device globals; no allocation) ----------------
__device__ uint2 d_g1[NNODES * 16];    // u1 = x @ W1, bf16x4 per uint2 (64 vals/row)
__device__ float d_h1[NNODES * F1];    // relu layer-1 output (fp32, GEMM2 input)
__device__ uint2 d_g2[NNODES * 10];    // u2 = h1 @ W2, bf16 (40 vals/row)
__device__ float d_h2[NNODES * F2];
__device__ float d_colsum[64];
__device__ float d_dinv[NNODES];
__device__ int   d_csrc[NEDGES];
__device__ int   d_cnt[NNODES];        // zero at t=0; re-zeroed by k_scan_lb each run
__device__ int   d_rowptr[NNODES + 1];
__device__ int   d_cursor[NNODES];
__device__ unsigned d_descr[LBN];      // lookback descriptors; reset by k_count each run

// ---------------- per-block int64/int32 detection helper ----------------
__device__ __forceinline__ int detect_is64(const void* e, int t) {
    __shared__ int s_is64;
    if (t < 32) {
        const long long* e64 = (const long long*)e;
        long long v0 = e64[t];
        long long v1 = e64[t + 32];
        bool ok = (v0 >= 0 && v0 < NNODES) && (v1 >= 0 && v1 < NNODES);
        unsigned m = __ballot_sync(0xffffffffu, ok);
        if (t == 0) s_is64 = (m == 0xffffffffu) ? 1 : 0;
    }
    __syncthreads();
    return s_is64;
}

// ---------------- per-dst histogram (reads raw edge list) + descr reset ----------------
__global__ void k_count(const void* __restrict__ e) {
    int t = threadIdx.x;
    if (blockIdx.x == 0 && t < LBN) d_descr[t] = 0u;   // reset lookback state
    int is64 = detect_is64(e, t);
    int idx = blockIdx.x * blockDim.x + t;
    if (idx >= NEDGES) return;
    int d = is64 ? (int)((const long long*)e)[NEDGES + idx]
                 : ((const int*)e)[NEDGES + idx];
    atomicAdd(&d_cnt[d], 1);
}

// ---------------- single-kernel decoupled-lookback exclusive scan ----------------
// grid = LBN (98) blocks x 1024 threads, all co-resident on 148 SMs.
__global__ __launch_bounds__(LBB) void k_scan_lb() {
    __shared__ int sm[LBB];
    __shared__ int s_prefix;
    int bid = blockIdx.x, t = threadIdx.x;
    int i = bid * LBB + t;
    int v = (i < NNODES) ? d_cnt[i] : 0;
    sm[t] = v;
    __syncthreads();
    for (int o = 1; o < LBB; o <<= 1) {
        int a = (t >= o) ? sm[t - o] : 0;
        __syncthreads();
        sm[t] += a;
        __syncthreads();
    }
    int incl = sm[t];
    int total = sm[LBB - 1];
    if (t == 0) {
        unsigned d = (bid == 0) ? ((2u << 30) | (unsigned)total)
                                : ((1u << 30) | (unsigned)total);
        __threadfence();
        *(volatile unsigned*)&d_descr[bid] = d;
        if (bid == 0) s_prefix = 0;
    }
    if (bid > 0 && t < 32) {
        int prefix = 0;
        int p = bid - 1;
        while (true) {
            int idx = p - t;
            unsigned d;
            if (idx >= 0) {
                do { d = *(volatile unsigned*)&d_descr[idx]; } while ((d >> 30) == 0u);
            } else {
                d = (2u << 30);
            }
            unsigned flag = d >> 30;
            int val = (int)(d & 0x3FFFFFFFu);
            unsigned m2 = __ballot_sync(0xffffffffu, flag == 2u);
            if (m2) {
                int firstIncl = __ffs(m2) - 1;
                int contrib = (t <= firstIncl) ? val : 0;
#pragma unroll
                for (int o = 16; o; o >>= 1) contrib += __shfl_xor_sync(0xffffffffu, contrib, o);
                prefix += contrib;
                break;
            } else {
                int contrib = val;
#pragma unroll
                for (int o = 16; o; o >>= 1) contrib += __shfl_xor_sync(0xffffffffu, contrib, o);
                prefix += contrib;
                p -= 32;
            }
        }
        if (t == 0) {
            __threadfence();
            *(volatile unsigned*)&d_descr[bid] = (2u << 30) | (unsigned)(prefix + total);
            s_prefix = prefix;
        }
    }
    __syncthreads();
    int ex = s_prefix + incl - v;
    if (i < NNODES) {
        d_rowptr[i] = ex;
        d_cursor[i] = ex;
        d_dinv[i] = rsqrtf(1.0f + (float)v);
        d_cnt[i] = 0;               // reset for next graph replay
    }
    if (i == 0) d_rowptr[NNODES] = NEDGES;
    if (bid == 0 && t < 64) d_colsum[t] = 0.f;
}

// ---------------- fill CSR (reads raw edge list) ----------------
__global__ void k_fill(const void* __restrict__ e) {
    int t = threadIdx.x;
    int is64 = detect_is64(e, t);
    int idx = blockIdx.x * blockDim.x + t;
    if (idx >= NEDGES) return;
    int s, d;
    if (is64) {
        s = (int)((const long long*)e)[idx];
        d = (int)((const long long*)e)[NEDGES + idx];
    } else {
        s = ((const int*)e)[idx];
        d = ((const int*)e)[NEDGES + idx];
    }
    int pos = atomicAdd(&d_cursor[d], 1);
    d_csrc[pos] = s;
}

// ---------------- TF32 GEMM with cp.async double buffering: C = A@B ----------------
#define CP_A16(dst, src, sz) \
    asm volatile("cp.async.ca.shared.global [%0], [%1], 16, %2;" \
                 :: "r"(dst), "l"(src), "r"(sz))

template <bool BF16OUT>
__global__ __launch_bounds__(256) void k_gemm_tf32(
    const float* __restrict__ A, const float* __restrict__ B,
    void* __restrict__ C, int M, int N, int K) {
    const int BM = 128, BK = 16, PA = 4, PB = 8;
    __shared__ float As[2][BM][BK + PA];
    __shared__ float Bs[2][BK][64 + PB];
    int tid = threadIdx.x;
    int rowBase = blockIdx.x * BM;
    int warpId = tid >> 5, lane = tid & 31;
    int g = lane >> 2, t4 = lane & 3;
    int m0 = (warpId & 3) * 32, n0 = (warpId >> 2) * 32;

    int ar0 = tid >> 2;
    int ac  = (tid & 3) * 4;
    int br  = tid >> 4;
    int bc  = (tid & 15) * 4;

    float acc[2][4][4];
#pragma unroll
    for (int mt = 0; mt < 2; mt++)
#pragma unroll
        for (int nt = 0; nt < 4; nt++)
#pragma unroll
            for (int i = 0; i < 4; i++) acc[mt][nt][i] = 0.f;

    int nIter = K / BK;

    auto prefetch = [&](int it, int st) {
#pragma unroll
        for (int v = 0; v < 2; v++) {
            int row = ar0 + v * 64;
            int gr = rowBase + row;
            unsigned dst = (unsigned)__cvta_generic_to_shared(&As[st][row][ac]);
            const float* src = A + (size_t)(gr < M ? gr : 0) * K + it * BK + ac;
            CP_A16(dst, src, (gr < M) ? 16 : 0);
        }
        {
            unsigned dst = (unsigned)__cvta_generic_to_shared(&Bs[st][br][bc]);
            int ok = (bc + 3 < N);
            const float* src = B + (size_t)(it * BK + br) * N + (ok ? bc : 0);
            CP_A16(dst, src, ok ? 16 : 0);
        }
    };

    prefetch(0, 0);
    asm volatile("cp.async.commit_group;" ::: "memory");

    for (int it = 0; it < nIter; it++) {
        int st = it & 1;
        if (it + 1 < nIter) {
            prefetch(it + 1, st ^ 1);
            asm volatile("cp.async.commit_group;" ::: "memory");
            asm volatile("cp.async.wait_group 1;" ::: "memory");
        } else {
            asm volatile("cp.async.wait_group 0;" ::: "memory");
        }
        __syncthreads();
#pragma unroll
        for (int ks = 0; ks < 2; ks++) {
            int kb = ks * 8;
            unsigned af[2][4], bf[4][2];
#pragma unroll
            for (int mt = 0; mt < 2; mt++) {
                int m = m0 + mt * 16 + g;
                af[mt][0] = __float_as_uint(As[st][m][kb + t4]);
                af[mt][1] = __float_as_uint(As[st][m + 8][kb + t4]);
                af[mt][2] = __float_as_uint(As[st][m][kb + t4 + 4]);
                af[mt][3] = __float_as_uint(As[st][m + 8][kb + t4 + 4]);
            }
#pragma unroll
            for (int nt = 0; nt < 4; nt++) {
                int n = n0 + nt * 8 + g;
                bf[nt][0] = __float_as_uint(Bs[st][kb + t4][n]);
                bf[nt][1] = __float_as_uint(Bs[st][kb + t4 + 4][n]);
            }
#pragma unroll
            for (int mt = 0; mt < 2; mt++)
#pragma unroll
                for (int nt = 0; nt < 4; nt++) {
                    asm volatile(
                        "mma.sync.aligned.m16n8k8.row.col.f32.tf32.tf32.f32 "
                        "{%0,%1,%2,%3}, {%4,%5,%6,%7}, {%8,%9}, {%0,%1,%2,%3};"
                        : "+f"(acc[mt][nt][0]), "+f"(acc[mt][nt][1]),
                          "+f"(acc[mt][nt][2]), "+f"(acc[mt][nt][3])
                        : "r"(af[mt][0]), "r"(af[mt][1]), "r"(af[mt][2]), "r"(af[mt][3]),
                          "r"(bf[nt][0]), "r"(bf[nt][1]));
                }
        }
        __syncthreads();
    }

#pragma unroll
    for (int mt = 0; mt < 2; mt++) {
#pragma unroll
        for (int half = 0; half < 2; half++) {
            int r = rowBase + m0 + mt * 16 + half * 8 + g;
            if (r >= M) continue;
#pragma unroll
            for (int nt = 0; nt < 4; nt++) {
                int c = n0 + nt * 8 + 2 * t4;
                if (c < N) {
                    float ox = acc[mt][nt][half * 2 + 0];
                    float oy = acc[mt][nt][half * 2 + 1];
                    if (BF16OUT) {
                        __nv_bfloat162 p = __float22bfloat162_rn(make_float2(ox, oy));
                        ((unsigned*)C)[(size_t)r * (N / 2) + (c >> 1)] = *(unsigned*)&p;
                    } else {
                        *(float2*)((float*)C + (size_t)r * N + c) = make_float2(ox, oy);
                    }
                }
            }
        }
    }
}

// ---------------- bf16x4 -> float4 helper ----------------
__device__ __forceinline__ float4 bf16x4_to_f4(uint2 raw) {
    float2 a = __bfloat1622float2(*(__nv_bfloat162*)&raw.x);
    float2 b = __bfloat1622float2(*(__nv_bfloat162*)&raw.y);
    return make_float4(a.x, a.y, b.x, b.y);
}

// ---------------- layer-1 aggregation: bf16 gather + self + bias + relu ----------------
__global__ __launch_bounds__(256) void k_agg1(const float* __restrict__ b1) {
    int g = (blockIdx.x * blockDim.x + threadIdx.x) >> 4;
    int lane = threadIdx.x & 15;
    if (g >= NNODES) return;
    int start = d_rowptr[g];
    int end = d_rowptr[g + 1];
    float sd = d_dinv[g];
    float4 u = bf16x4_to_f4(__ldg(&d_g1[(size_t)g * 16 + lane]));
    float4 acc = make_float4(sd * u.x, sd * u.y, sd * u.z, sd * u.w);  // self loop
    int e = start;
    for (; e + 3 < end; e += 4) {
        int s0 = __ldg(&d_csrc[e]);
        int s1 = __ldg(&d_csrc[e + 1]);
        int s2 = __ldg(&d_csrc[e + 2]);
        int s3 = __ldg(&d_csrc[e + 3]);
        float w0 = __ldg(&d_dinv[s0]);
        float w1 = __ldg(&d_dinv[s1]);
        float w2 = __ldg(&d_dinv[s2]);
        float w3 = __ldg(&d_dinv[s3]);
        float4 v0 = bf16x4_to_f4(__ldg(&d_g1[(size_t)s0 * 16 + lane]));
        float4 v1 = bf16x4_to_f4(__ldg(&d_g1[(size_t)s1 * 16 + lane]));
        float4 v2 = bf16x4_to_f4(__ldg(&d_g1[(size_t)s2 * 16 + lane]));
        float4 v3 = bf16x4_to_f4(__ldg(&d_g1[(size_t)s3 * 16 + lane]));
        acc.x += w0 * v0.x + w1 * v1.x + w2 * v2.x + w3 * v3.x;
        acc.y += w0 * v0.y + w1 * v1.y + w2 * v2.y + w3 * v3.y;
        acc.z += w0 * v0.z + w1 * v1.z + w2 * v2.z + w3 * v3.z;
        acc.w += w0 * v0.w + w1 * v1.w + w2 * v2.w + w3 * v3.w;
    }
    for (; e < end; e++) {
        int s0 = __ldg(&d_csrc[e]);
        float w0 = __ldg(&d_dinv[s0]);
        float4 v = bf16x4_to_f4(__ldg(&d_g1[(size_t)s0 * 16 + lane]));
        acc.x += w0 * v.x; acc.y += w0 * v.y; acc.z += w0 * v.z; acc.w += w0 * v.w;
    }
    int c = lane * 4;
    float4 o;
    o.x = fmaxf(sd * acc.x + __ldg(b1 + c + 0), 0.f);
    o.y = fmaxf(sd * acc.y + __ldg(b1 + c + 1), 0.f);
    o.z = fmaxf(sd * acc.z + __ldg(b1 + c + 2), 0.f);
    o.w = fmaxf(sd * acc.w + __ldg(b1 + c + 3), 0.f);
    ((float4*)d_h1)[(size_t)g * 16 + lane] = o;
}

// ---------------- layer-2 aggregation + bias + column sums ----------------
__global__ __launch_bounds__(256) void k_agg2(const float* __restrict__ b2) {
    __shared__ float scol[F2];
    int t = threadIdx.x;
    if (t < F2) scol[t] = 0.f;
    __syncthreads();
    int g = (blockIdx.x * blockDim.x + t) >> 4;
    int lane = t & 15;
    bool active = (g < NNODES) && (lane < 10);
    if (active) {
        int start = d_rowptr[g];
        int end = d_rowptr[g + 1];
        float sd = d_dinv[g];
        float4 u = bf16x4_to_f4(__ldg(&d_g2[(size_t)g * 10 + lane]));
        float4 acc = make_float4(sd * u.x, sd * u.y, sd * u.z, sd * u.w);
        int e = start;
        for (; e + 1 < end; e += 2) {
            int s0 = __ldg(&d_csrc[e]);
            int s1 = __ldg(&d_csrc[e + 1]);
            float w0 = __ldg(&d_dinv[s0]);
            float w1 = __ldg(&d_dinv[s1]);
            float4 v0 = bf16x4_to_f4(__ldg(&d_g2[(size_t)s0 * 10 + lane]));
            float4 v1 = bf16x4_to_f4(__ldg(&d_g2[(size_t)s1 * 10 + lane]));
            acc.x += w0 * v0.x + w1 * v1.x;
            acc.y += w0 * v0.y + w1 * v1.y;
            acc.z += w0 * v0.z + w1 * v1.z;
            acc.w += w0 * v0.w + w1 * v1.w;
        }
        if (e < end) {
            int s0 = __ldg(&d_csrc[e]);
            float w0 = __ldg(&d_dinv[s0]);
            float4 v = bf16x4_to_f4(__ldg(&d_g2[(size_t)s0 * 10 + lane]));
            acc.x += w0 * v.x; acc.y += w0 * v.y; acc.z += w0 * v.z; acc.w += w0 * v.w;
        }
        int c = lane * 4;
        float4 o;
        o.x = sd * acc.x + __ldg(b2 + c + 0);
        o.y = sd * acc.y + __ldg(b2 + c + 1);
        o.z = sd * acc.z + __ldg(b2 + c + 2);
        o.w = sd * acc.w + __ldg(b2 + c + 3);
        ((float4*)d_h2)[(size_t)g * 10 + lane] = o;
        atomicAdd(&scol[c + 0], o.x);
        atomicAdd(&scol[c + 1], o.y);
        atomicAdd(&scol[c + 2], o.z);
        atomicAdd(&scol[c + 3], o.w);
    }
    __syncthreads();
    if (t < F2) atomicAdd(&d_colsum[t], scol[t]);
}

// ---------------- PairNorm-SI + log_softmax, one warp per row ----------------
__global__ void k_final(float* __restrict__ out) {
    int gt = blockIdx.x * blockDim.x + threadIdx.x;
    int row = gt >> 5;
    int lane = gt & 31;
    if (row >= NNODES) return;
    const float invN = 1.0f / (float)NNODES;
    bool has2 = lane < (F2 - 32);
    float y0 = d_h2[(size_t)row * F2 + lane] - d_colsum[lane] * invN;
    float y1 = 0.f;
    if (has2) y1 = d_h2[(size_t)row * F2 + 32 + lane] - d_colsum[32 + lane] * invN;
    float ss = y0 * y0 + y1 * y1;
#pragma unroll
    for (int o = 16; o; o >>= 1) ss += __shfl_xor_sync(0xffffffffu, ss, o);
    float inv = rsqrtf(1e-6f + ss);
    float z0 = y0 * inv;
    float z1 = has2 ? y1 * inv : -1e30f;
    float mx = fmaxf(z0, z1);
#pragma unroll
    for (int o = 16; o; o >>= 1) mx = fmaxf(mx, __shfl_xor_sync(0xffffffffu, mx, o));
    float se = expf(z0 - mx) + (has2 ? expf(z1 - mx) : 0.f);
#pragma unroll
    for (int o = 16; o; o >>= 1) se += __shfl_xor_sync(0xffffffffu, se, o);
    float lse = logf(se);
    out[(size_t)row * F2 + lane] = z0 - mx - lse;
    if (has2) out[(size_t)row * F2 + 32 + lane] = z1 - mx - lse;
}

// ---------------- launch ----------------
extern "C" void kernel_launch(void* const* d_in, const int* in_sizes, int n_in,
                              void* d_out, int out_size) {
    const float* x   = (const float*)d_in[0];
    const void*  eix = d_in[1];
    const float* W1  = (const float*)d_in[2];
    const float* b1  = (const float*)d_in[3];
    const float* W2  = (const float*)d_in[4];
    const float* b2  = (const float*)d_in[5];
    float* out = (float*)d_out;

    static cudaStream_t s_aux = []() {
        cudaStream_t s; cudaStreamCreateWithFlags(&s, cudaStreamNonBlocking); return s;
    }();
    static cudaEvent_t e_fork = []() {
        cudaEvent_t e; cudaEventCreateWithFlags(&e, cudaEventDisableTiming); return e;
    }();
    static cudaEvent_t e_join = []() {
        cudaEvent_t e; cudaEventCreateWithFlags(&e, cudaEventDisableTiming); return e;
    }();

    void *g1, *g2;
    float *h1;
    cudaGetSymbolAddress(&g1, d_g1);
    cudaGetSymbolAddress((void**)&h1, d_h1);
    cudaGetSymbolAddress(&g2, d_g2);

    const int T = 256;

    // Fork: GEMM1 enqueued FIRST on aux stream so it wins SMs and overlaps CSR build
    cudaEventRecord(e_fork, 0);
    cudaStreamWaitEvent(s_aux, e_fork, 0);
    k_gemm_tf32<true><<<(NNODES + 127) / 128, 256, 0, s_aux>>>(x, W1, g1, NNODES, F1, F0);
    cudaEventRecord(e_join, s_aux);

    // CSR build on the main stream (3 kernels; k_fill = API #4 -> ncu captures it)
    k_count<<<(NEDGES + T - 1) / T, T>>>(eix);
    k_scan_lb<<<LBN, LBB>>>();
    k_fill<<<(NEDGES + T - 1) / T, T>>>(eix);

    // Join, then the dependent chain
    cudaStreamWaitEvent(0, e_join, 0);
    k_agg1<<<(NNODES * 16 + T - 1) / T, T>>>(b1);
    k_gemm_tf32<true><<<(NNODES + 127) / 128, 256>>>(h1, W2, g2, NNODES, F2, F1);
    k_agg2<<<(NNODES * 16 + T - 1) / T, T>>>(b2);
    k_final<<<((long long)NNODES * 32 + T - 1) / T, T>>>(out);
}

// round 17
// speedup vs baseline: 1.1085x; 1.0230x over previous
#include <cuda_runtime.h>
#include <cuda_bf16.h>
#include <math.h>

#define NNODES 100000
#define NEDGES 1000000
#define F0 256
#define F1 64
#define F2 40
#define LBB 1024
#define LBN ((NNODES + LBB - 1) / LBB)   // 98 partitions

// ---------------- scratch (static device globals; no allocation) ----------------
__device__ uint2 d_g1[NNODES * 16];    // u1 = x @ W1, bf16x4 per uint2 (64 vals/row)
__device__ float d_h1[NNODES * F1];    // relu layer-1 output (fp32, GEMM2 input)
__device__ uint2 d_g2[NNODES * 10];    // u2 = h1 @ W2, bf16 (40 vals/row)
__device__ float d_h2[NNODES * F2];
__device__ float d_colsum[64];
__device__ float d_dinv[NNODES];
__device__ int   d_csrc[NEDGES];
__device__ int   d_rank[NEDGES];       // arrival rank of edge within its dst bucket
__device__ int   d_cnt[NNODES];        // zero at t=0; re-zeroed by k_scan_lb each run
__device__ int   d_rowptr[NNODES + 1];
__device__ unsigned d_descr[LBN];      // lookback descriptors; reset by k_count each run

// ---------------- per-block int64/int32 detection helper ----------------
__device__ __forceinline__ int detect_is64(const void* e, int t) {
    __shared__ int s_is64;
    if (t < 32) {
        const long long* e64 = (const long long*)e;
        long long v0 = e64[t];
        long long v1 = e64[t + 32];
        bool ok = (v0 >= 0 && v0 < NNODES) && (v1 >= 0 && v1 < NNODES);
        unsigned m = __ballot_sync(0xffffffffu, ok);
        if (t == 0) s_is64 = (m == 0xffffffffu) ? 1 : 0;
    }
    __syncthreads();
    return s_is64;
}

// ---------------- per-dst histogram + rank capture (reads raw edge list) ----------------
__global__ void k_count(const void* __restrict__ e) {
    int t = threadIdx.x;
    if (blockIdx.x == 0 && t < LBN) d_descr[t] = 0u;   // reset lookback state
    int is64 = detect_is64(e, t);
    int idx = blockIdx.x * blockDim.x + t;
    if (idx >= NEDGES) return;
    int d = is64 ? (int)((const long long*)e)[NEDGES + idx]
                 : ((const int*)e)[NEDGES + idx];
    d_rank[idx] = atomicAdd(&d_cnt[d], 1);             // rank doubles as fill position
}

// ---------------- single-kernel decoupled-lookback exclusive scan ----------------
__global__ __launch_bounds__(LBB) void k_scan_lb() {
    __shared__ int sm[LBB];
    __shared__ int s_prefix;
    int bid = blockIdx.x, t = threadIdx.x;
    int i = bid * LBB + t;
    int v = (i < NNODES) ? d_cnt[i] : 0;
    sm[t] = v;
    __syncthreads();
    for (int o = 1; o < LBB; o <<= 1) {
        int a = (t >= o) ? sm[t - o] : 0;
        __syncthreads();
        sm[t] += a;
        __syncthreads();
    }
    int incl = sm[t];
    int total = sm[LBB - 1];
    if (t == 0) {
        unsigned d = (bid == 0) ? ((2u << 30) | (unsigned)total)
                                : ((1u << 30) | (unsigned)total);
        __threadfence();
        *(volatile unsigned*)&d_descr[bid] = d;
        if (bid == 0) s_prefix = 0;
    }
    if (bid > 0 && t < 32) {
        int prefix = 0;
        int p = bid - 1;
        while (true) {
            int idx = p - t;
            unsigned d;
            if (idx >= 0) {
                do { d = *(volatile unsigned*)&d_descr[idx]; } while ((d >> 30) == 0u);
            } else {
                d = (2u << 30);
            }
            unsigned flag = d >> 30;
            int val = (int)(d & 0x3FFFFFFFu);
            unsigned m2 = __ballot_sync(0xffffffffu, flag == 2u);
            if (m2) {
                int firstIncl = __ffs(m2) - 1;
                int contrib = (t <= firstIncl) ? val : 0;
#pragma unroll
                for (int o = 16; o; o >>= 1) contrib += __shfl_xor_sync(0xffffffffu, contrib, o);
                prefix += contrib;
                break;
            } else {
                int contrib = val;
#pragma unroll
                for (int o = 16; o; o >>= 1) contrib += __shfl_xor_sync(0xffffffffu, contrib, o);
                prefix += contrib;
                p -= 32;
            }
        }
        if (t == 0) {
            __threadfence();
            *(volatile unsigned*)&d_descr[bid] = (2u << 30) | (unsigned)(prefix + total);
            s_prefix = prefix;
        }
    }
    __syncthreads();
    int ex = s_prefix + incl - v;
    if (i < NNODES) {
        d_rowptr[i] = ex;
        d_dinv[i] = rsqrtf(1.0f + (float)v);
        d_cnt[i] = 0;               // reset for next graph replay
    }
    if (i == 0) d_rowptr[NNODES] = NEDGES;
    if (bid == 0 && t < 64) d_colsum[t] = 0.f;
}

// ---------------- fill CSR (atomic-free: pos = rowptr[dst] + rank) ----------------
__global__ void k_fill(const void* __restrict__ e) {
    int t = threadIdx.x;
    int is64 = detect_is64(e, t);
    int idx = blockIdx.x * blockDim.x + t;
    if (idx >= NEDGES) return;
    int s, d;
    if (is64) {
        s = (int)((const long long*)e)[idx];
        d = (int)((const long long*)e)[NEDGES + idx];
    } else {
        s = ((const int*)e)[idx];
        d = ((const int*)e)[NEDGES + idx];
    }
    int pos = __ldg(&d_rowptr[d]) + d_rank[idx];
    d_csrc[pos] = s;
}

// ---------------- TF32 GEMM with cp.async double buffering: C = A@B ----------------
#define CP_A16(dst, src, sz) \
    asm volatile("cp.async.ca.shared.global [%0], [%1], 16, %2;" \
                 :: "r"(dst), "l"(src), "r"(sz))

template <bool BF16OUT>
__global__ __launch_bounds__(256) void k_gemm_tf32(
    const float* __restrict__ A, const float* __restrict__ B,
    void* __restrict__ C, int M, int N, int K) {
    const int BM = 128, BK = 16, PA = 4, PB = 8;
    __shared__ float As[2][BM][BK + PA];
    __shared__ float Bs[2][BK][64 + PB];
    int tid = threadIdx.x;
    int rowBase = blockIdx.x * BM;
    int warpId = tid >> 5, lane = tid & 31;
    int g = lane >> 2, t4 = lane & 3;
    int m0 = (warpId & 3) * 32, n0 = (warpId >> 2) * 32;

    int ar0 = tid >> 2;
    int ac  = (tid & 3) * 4;
    int br  = tid >> 4;
    int bc  = (tid & 15) * 4;

    float acc[2][4][4];
#pragma unroll
    for (int mt = 0; mt < 2; mt++)
#pragma unroll
        for (int nt = 0; nt < 4; nt++)
#pragma unroll
            for (int i = 0; i < 4; i++) acc[mt][nt][i] = 0.f;

    int nIter = K / BK;

    auto prefetch = [&](int it, int st) {
#pragma unroll
        for (int v = 0; v < 2; v++) {
            int row = ar0 + v * 64;
            int gr = rowBase + row;
            unsigned dst = (unsigned)__cvta_generic_to_shared(&As[st][row][ac]);
            const float* src = A + (size_t)(gr < M ? gr : 0) * K + it * BK + ac;
            CP_A16(dst, src, (gr < M) ? 16 : 0);
        }
        {
            unsigned dst = (unsigned)__cvta_generic_to_shared(&Bs[st][br][bc]);
            int ok = (bc + 3 < N);
            const float* src = B + (size_t)(it * BK + br) * N + (ok ? bc : 0);
            CP_A16(dst, src, ok ? 16 : 0);
        }
    };

    prefetch(0, 0);
    asm volatile("cp.async.commit_group;" ::: "memory");

    for (int it = 0; it < nIter; it++) {
        int st = it & 1;
        if (it + 1 < nIter) {
            prefetch(it + 1, st ^ 1);
            asm volatile("cp.async.commit_group;" ::: "memory");
            asm volatile("cp.async.wait_group 1;" ::: "memory");
        } else {
            asm volatile("cp.async.wait_group 0;" ::: "memory");
        }
        __syncthreads();
#pragma unroll
        for (int ks = 0; ks < 2; ks++) {
            int kb = ks * 8;
            unsigned af[2][4], bf[4][2];
#pragma unroll
            for (int mt = 0; mt < 2; mt++) {
                int m = m0 + mt * 16 + g;
                af[mt][0] = __float_as_uint(As[st][m][kb + t4]);
                af[mt][1] = __float_as_uint(As[st][m + 8][kb + t4]);
                af[mt][2] = __float_as_uint(As[st][m][kb + t4 + 4]);
                af[mt][3] = __float_as_uint(As[st][m + 8][kb + t4 + 4]);
            }
#pragma unroll
            for (int nt = 0; nt < 4; nt++) {
                int n = n0 + nt * 8 + g;
                bf[nt][0] = __float_as_uint(Bs[st][kb + t4][n]);
                bf[nt][1] = __float_as_uint(Bs[st][kb + t4 + 4][n]);
            }
#pragma unroll
            for (int mt = 0; mt < 2; mt++)
#pragma unroll
                for (int nt = 0; nt < 4; nt++) {
                    asm volatile(
                        "mma.sync.aligned.m16n8k8.row.col.f32.tf32.tf32.f32 "
                        "{%0,%1,%2,%3}, {%4,%5,%6,%7}, {%8,%9}, {%0,%1,%2,%3};"
                        : "+f"(acc[mt][nt][0]), "+f"(acc[mt][nt][1]),
                          "+f"(acc[mt][nt][2]), "+f"(acc[mt][nt][3])
                        : "r"(af[mt][0]), "r"(af[mt][1]), "r"(af[mt][2]), "r"(af[mt][3]),
                          "r"(bf[nt][0]), "r"(bf[nt][1]));
                }
        }
        __syncthreads();
    }

#pragma unroll
    for (int mt = 0; mt < 2; mt++) {
#pragma unroll
        for (int half = 0; half < 2; half++) {
            int r = rowBase + m0 + mt * 16 + half * 8 + g;
            if (r >= M) continue;
#pragma unroll
            for (int nt = 0; nt < 4; nt++) {
                int c = n0 + nt * 8 + 2 * t4;
                if (c < N) {
                    float ox = acc[mt][nt][half * 2 + 0];
                    float oy = acc[mt][nt][half * 2 + 1];
                    if (BF16OUT) {
                        __nv_bfloat162 p = __float22bfloat162_rn(make_float2(ox, oy));
                        ((unsigned*)C)[(size_t)r * (N / 2) + (c >> 1)] = *(unsigned*)&p;
                    } else {
                        *(float2*)((float*)C + (size_t)r * N + c) = make_float2(ox, oy);
                    }
                }
            }
        }
    }
}

// ---------------- bf16x4 -> float4 helper ----------------
__device__ __forceinline__ float4 bf16x4_to_f4(uint2 raw) {
    float2 a = __bfloat1622float2(*(__nv_bfloat162*)&raw.x);
    float2 b = __bfloat1622float2(*(__nv_bfloat162*)&raw.y);
    return make_float4(a.x, a.y, b.x, b.y);
}

// ---------------- layer-1 aggregation: bf16 gather + self + bias + relu ----------------
__global__ __launch_bounds__(256) void k_agg1(const float* __restrict__ b1) {
    int g = (blockIdx.x * blockDim.x + threadIdx.x) >> 4;
    int lane = threadIdx.x & 15;
    if (g >= NNODES) return;
    int start = d_rowptr[g];
    int end = d_rowptr[g + 1];
    float sd = d_dinv[g];
    float4 u = bf16x4_to_f4(__ldg(&d_g1[(size_t)g * 16 + lane]));
    float4 acc = make_float4(sd * u.x, sd * u.y, sd * u.z, sd * u.w);  // self loop
    int e = start;
    for (; e + 3 < end; e += 4) {
        int s0 = __ldg(&d_csrc[e]);
        int s1 = __ldg(&d_csrc[e + 1]);
        int s2 = __ldg(&d_csrc[e + 2]);
        int s3 = __ldg(&d_csrc[e + 3]);
        float w0 = __ldg(&d_dinv[s0]);
        float w1 = __ldg(&d_dinv[s1]);
        float w2 = __ldg(&d_dinv[s2]);
        float w3 = __ldg(&d_dinv[s3]);
        float4 v0 = bf16x4_to_f4(__ldg(&d_g1[(size_t)s0 * 16 + lane]));
        float4 v1 = bf16x4_to_f4(__ldg(&d_g1[(size_t)s1 * 16 + lane]));
        float4 v2 = bf16x4_to_f4(__ldg(&d_g1[(size_t)s2 * 16 + lane]));
        float4 v3 = bf16x4_to_f4(__ldg(&d_g1[(size_t)s3 * 16 + lane]));
        acc.x += w0 * v0.x + w1 * v1.x + w2 * v2.x + w3 * v3.x;
        acc.y += w0 * v0.y + w1 * v1.y + w2 * v2.y + w3 * v3.y;
        acc.z += w0 * v0.z + w1 * v1.z + w2 * v2.z + w3 * v3.z;
        acc.w += w0 * v0.w + w1 * v1.w + w2 * v2.w + w3 * v3.w;
    }
    for (; e < end; e++) {
        int s0 = __ldg(&d_csrc[e]);
        float w0 = __ldg(&d_dinv[s0]);
        float4 v = bf16x4_to_f4(__ldg(&d_g1[(size_t)s0 * 16 + lane]));
        acc.x += w0 * v.x; acc.y += w0 * v.y; acc.z += w0 * v.z; acc.w += w0 * v.w;
    }
    int c = lane * 4;
    float4 o;
    o.x = fmaxf(sd * acc.x + __ldg(b1 + c + 0), 0.f);
    o.y = fmaxf(sd * acc.y + __ldg(b1 + c + 1), 0.f);
    o.z = fmaxf(sd * acc.z + __ldg(b1 + c + 2), 0.f);
    o.w = fmaxf(sd * acc.w + __ldg(b1 + c + 3), 0.f);
    ((float4*)d_h1)[(size_t)g * 16 + lane] = o;
}

// ---------------- layer-2 aggregation + bias + column sums ----------------
__global__ __launch_bounds__(256) void k_agg2(const float* __restrict__ b2) {
    __shared__ float scol[F2];
    int t = threadIdx.x;
    if (t < F2) scol[t] = 0.f;
    __syncthreads();
    int g = (blockIdx.x * blockDim.x + t) >> 4;
    int lane = t & 15;
    bool active = (g < NNODES) && (lane < 10);
    if (active) {
        int start = d_rowptr[g];
        int end = d_rowptr[g + 1];
        float sd = d_dinv[g];
        float4 u = bf16x4_to_f4(__ldg(&d_g2[(size_t)g * 10 + lane]));
        float4 acc = make_float4(sd * u.x, sd * u.y, sd * u.z, sd * u.w);
        int e = start;
        for (; e + 1 < end; e += 2) {
            int s0 = __ldg(&d_csrc[e]);
            int s1 = __ldg(&d_csrc[e + 1]);
            float w0 = __ldg(&d_dinv[s0]);
            float w1 = __ldg(&d_dinv[s1]);
            float4 v0 = bf16x4_to_f4(__ldg(&d_g2[(size_t)s0 * 10 + lane]));
            float4 v1 = bf16x4_to_f4(__ldg(&d_g2[(size_t)s1 * 10 + lane]));
            acc.x += w0 * v0.x + w1 * v1.x;
            acc.y += w0 * v0.y + w1 * v1.y;
            acc.z += w0 * v0.z + w1 * v1.z;
            acc.w += w0 * v0.w + w1 * v1.w;
        }
        if (e < end) {
            int s0 = __ldg(&d_csrc[e]);
            float w0 = __ldg(&d_dinv[s0]);
            float4 v = bf16x4_to_f4(__ldg(&d_g2[(size_t)s0 * 10 + lane]));
            acc.x += w0 * v.x; acc.y += w0 * v.y; acc.z += w0 * v.z; acc.w += w0 * v.w;
        }
        int c = lane * 4;
        float4 o;
        o.x = sd * acc.x + __ldg(b2 + c + 0);
        o.y = sd * acc.y + __ldg(b2 + c + 1);
        o.z = sd * acc.z + __ldg(b2 + c + 2);
        o.w = sd * acc.w + __ldg(b2 + c + 3);
        ((float4*)d_h2)[(size_t)g * 10 + lane] = o;
        atomicAdd(&scol[c + 0], o.x);
        atomicAdd(&scol[c + 1], o.y);
        atomicAdd(&scol[c + 2], o.z);
        atomicAdd(&scol[c + 3], o.w);
    }
    __syncthreads();
    if (t < F2) atomicAdd(&d_colsum[t], scol[t]);
}

// ---------------- PairNorm-SI + log_softmax, one warp per row ----------------
__global__ void k_final(float* __restrict__ out) {
    int gt = blockIdx.x * blockDim.x + threadIdx.x;
    int row = gt >> 5;
    int lane = gt & 31;
    if (row >= NNODES) return;
    const float invN = 1.0f / (float)NNODES;
    bool has2 = lane < (F2 - 32);
    float y0 = d_h2[(size_t)row * F2 + lane] - d_colsum[lane] * invN;
    float y1 = 0.f;
    if (has2) y1 = d_h2[(size_t)row * F2 + 32 + lane] - d_colsum[32 + lane] * invN;
    float ss = y0 * y0 + y1 * y1;
#pragma unroll
    for (int o = 16; o; o >>= 1) ss += __shfl_xor_sync(0xffffffffu, ss, o);
    float inv = rsqrtf(1e-6f + ss);
    float z0 = y0 * inv;
    float z1 = has2 ? y1 * inv : -1e30f;
    float mx = fmaxf(z0, z1);
#pragma unroll
    for (int o = 16; o; o >>= 1) mx = fmaxf(mx, __shfl_xor_sync(0xffffffffu, mx, o));
    float se = expf(z0 - mx) + (has2 ? expf(z1 - mx) : 0.f);
#pragma unroll
    for (int o = 16; o; o >>= 1) se += __shfl_xor_sync(0xffffffffu, se, o);
    float lse = logf(se);
    out[(size_t)row * F2 + lane] = z0 - mx - lse;
    if (has2) out[(size_t)row * F2 + 32 + lane] = z1 - mx - lse;
}

// ---------------- launch ----------------
extern "C" void kernel_launch(void* const* d_in, const int* in_sizes, int n_in,
                              void* d_out, int out_size) {
    const float* x   = (const float*)d_in[0];
    const void*  eix = d_in[1];
    const float* W1  = (const float*)d_in[2];
    const float* b1  = (const float*)d_in[3];
    const float* W2  = (const float*)d_in[4];
    const float* b2  = (const float*)d_in[5];
    float* out = (float*)d_out;

    static cudaStream_t s_aux = []() {
        cudaStream_t s; cudaStreamCreateWithFlags(&s, cudaStreamNonBlocking); return s;
    }();
    static cudaEvent_t e_fork = []() {
        cudaEvent_t e; cudaEventCreateWithFlags(&e, cudaEventDisableTiming); return e;
    }();
    static cudaEvent_t e_join = []() {
        cudaEvent_t e; cudaEventCreateWithFlags(&e, cudaEventDisableTiming); return e;
    }();

    void *g1, *g2;
    float *h1;
    cudaGetSymbolAddress(&g1, d_g1);
    cudaGetSymbolAddress((void**)&h1, d_h1);
    cudaGetSymbolAddress(&g2, d_g2);

    const int T = 256;

    // Fork: GEMM1 enqueued FIRST on aux stream so it wins SMs and overlaps CSR build
    cudaEventRecord(e_fork, 0);
    cudaStreamWaitEvent(s_aux, e_fork, 0);
    k_gemm_tf32<true><<<(NNODES + 127) / 128, 256, 0, s_aux>>>(x, W1, g1, NNODES, F1, F0);
    cudaEventRecord(e_join, s_aux);

    // CSR build on the main stream (atomic-free fill via rank)
    k_count<<<(NEDGES + T - 1) / T, T>>>(eix);
    k_scan_lb<<<LBN, LBB>>>();
    k_fill<<<(NEDGES + T - 1) / T, T>>>(eix);

    // Join, then the dependent chain
    cudaStreamWaitEvent(0, e_join, 0);
    k_agg1<<<(NNODES * 16 + T - 1) / T, T>>>(b1);
    k_gemm_tf32<true><<<(NNODES + 127) / 128, 256>>>(h1, W2, g2, NNODES, F2, F1);
    k_agg2<<<(NNODES * 16 + T - 1) / T, T>>>(b2);
    k_final<<<((long long)NNODES * 32 + T - 1) / T, T>>>(out);
}